// round 1
// baseline (speedup 1.0000x reference)
#include <cuda_runtime.h>

#define NP      3072
#define SPLITS  32
#define CHUNK   (NP / SPLITS)   // 96
#define TPB     128
#define JBLK    (NP / TPB)      // 24
#define TPB2    256
#define JBLK2   (NP / TPB2)     // 12

// constants (sigma = 1)
#define A_CONST 0.7071067811865476f            // 1/(sigma*sqrt(2))
#define C1      0.7978845608028654f            // 2A/sqrt(pi)
#define C3      0.7978845608028654f            // 4A^3/sqrt(pi)  (== C1 since A^2=0.5)
#define NC      14.399645f                      // 90.4756 / (2*pi)

// scratch: [SPLITS][6][NP] partial accumulators + per-block pot partials
__device__ float g_part[SPLITS * 6 * NP];
__device__ float g_potblk[JBLK2];

__global__ __launch_bounds__(TPB)
void ewald_pair_kernel(const float* __restrict__ q,
                       const float* __restrict__ r,
                       const float* __restrict__ u)
{
    const int j  = blockIdx.x * TPB + threadIdx.x;
    const int s  = blockIdx.y;
    const int i0 = s * CHUNK;

    __shared__ float srx[CHUNK], sry[CHUNK], srz[CHUNK], sq[CHUNK];
    __shared__ float sux[CHUNK], suy[CHUNK], suz[CHUNK];

    for (int t = threadIdx.x; t < CHUNK; t += TPB) {
        const int ig = i0 + t;
        srx[t] = r[3 * ig + 0];
        sry[t] = r[3 * ig + 1];
        srz[t] = r[3 * ig + 2];
        sq[t]  = q[ig];
        sux[t] = u[3 * ig + 0];
        suy[t] = u[3 * ig + 1];
        suz[t] = u[3 * ig + 2];
    }
    __syncthreads();

    const float rjx = r[3 * j + 0];
    const float rjy = r[3 * j + 1];
    const float rjz = r[3 * j + 2];
    const float ujx = u[3 * j + 0];
    const float ujy = u[3 * j + 1];
    const float ujz = u[3 * j + 2];

    float a1 = 0.f, a2 = 0.f, fx = 0.f, fy = 0.f, fz = 0.f, dd = 0.f;

#pragma unroll 4
    for (int t = 0; t < CHUNK; ++t) {
        const int ig = i0 + t;
        // r_ij = r_j - r_i
        float dx = rjx - srx[t];
        float dy = rjy - sry[t];
        float dz = rjz - srz[t];
        float d2 = dx * dx + dy * dy + dz * dz;

        const bool self = (ig == j);
        if (self) d2 = 1.0f;   // keep rsqrt finite; terms zeroed below

        const float rinv  = rsqrtf(d2);
        const float rn    = d2 * rinv;          // |r_ij|
        const float rinv2 = rinv * rinv;

        const float x  = A_CONST * rn;
        float er = erff(x);
        float g  = __expf(-x * x);
        if (self) { er = 0.f; g = 0.f; }

        const float erinv = er * rinv;                      // erf * rinv
        const float s1    = (erinv - C1 * g) * rinv2;       // erf*rinv^3 - c1*g*rinv^2
        const float s2v   = 3.f * s1 - C3 * g;              // algebraic identity

        const float qi = sq[t];
        a1 += qi * erinv;

        const float uix = sux[t], uiy = suy[t], uiz = suz[t];
        const float uri = uix * dx + uiy * dy + uiz * dz;   // u_i . r_ij
        a2 += s1 * uri;

        const float urj = ujx * dx + ujy * dy + ujz * dz;   // u_j . r_ij
        const float uu  = uix * ujx + uiy * ujy + uiz * ujz;
        const float s2r = s2v * uri * rinv2;
        dd += s2r * urj - s1 * uu;                          // s2*ai*bj - s1*uu

        const float tc = qi * s1 + s2r;                     // field coefficient on r_ij
        fx += tc * dx - s1 * uix;
        fy += tc * dy - s1 * uiy;
        fz += tc * dz - s1 * uiz;
    }

    float* p = g_part + (size_t)s * 6 * NP;
    p[0 * NP + j] = a1;
    p[1 * NP + j] = a2;
    p[2 * NP + j] = fx;
    p[3 * NP + j] = fy;
    p[4 * NP + j] = fz;
    p[5 * NP + j] = dd;
}

__global__ __launch_bounds__(TPB2)
void ewald_reduce_kernel(const float* __restrict__ q,
                         const float* __restrict__ kappa,
                         const float* __restrict__ alpha,
                         float* __restrict__ out)
{
    const int j = blockIdx.x * TPB2 + threadIdx.x;

    float a1 = 0.f, a2 = 0.f, fx = 0.f, fy = 0.f, fz = 0.f, dd = 0.f;
#pragma unroll
    for (int s = 0; s < SPLITS; ++s) {
        const float* p = g_part + (size_t)s * 6 * NP;
        a1 += p[0 * NP + j];
        a2 += p[1 * NP + j];
        fx += p[2 * NP + j];
        fy += p[3 * NP + j];
        fz += p[4 * NP + j];
        dd += p[5 * NP + j];
    }

    const float ka = kappa[j];
    const float al = alpha[j];
    const float qj = q[j];

    const float ephi = NC * (a1 + a2);
    const float qind = -ka * ephi;
    const float efx = NC * fx, efy = NC * fy, efz = NC * fz;

    out[1 + j] = qind;
    out[1 + NP + 3 * j + 0] = al * efx;
    out[1 + NP + 3 * j + 1] = al * efy;
    out[1 + NP + 3 * j + 2] = al * efz;

    float potj = qj * NC * (0.5f * a1 + a2)
               - 0.5f * NC * dd
               - 0.5f * ka * ephi * ephi
               - 0.5f * al * (efx * efx + efy * efy + efz * efz);

    // block reduction of potj
    __shared__ float sh[TPB2];
    sh[threadIdx.x] = potj;
    __syncthreads();
#pragma unroll
    for (int ofs = TPB2 / 2; ofs > 0; ofs >>= 1) {
        if (threadIdx.x < ofs) sh[threadIdx.x] += sh[threadIdx.x + ofs];
        __syncthreads();
    }
    if (threadIdx.x == 0) g_potblk[blockIdx.x] = sh[0];
}

__global__ void ewald_final_kernel(float* __restrict__ out)
{
    double v = 0.0;
    if (threadIdx.x < JBLK2) v = (double)g_potblk[threadIdx.x];
#pragma unroll
    for (int ofs = 16; ofs > 0; ofs >>= 1)
        v += __shfl_down_sync(0xFFFFFFFFu, v, ofs);
    if (threadIdx.x == 0) out[0] = (float)v;
}

extern "C" void kernel_launch(void* const* d_in, const int* in_sizes, int n_in,
                              void* d_out, int out_size)
{
    // inputs (metadata order): q[N], r[N,3], cell[1,3,3], batch[N], u[N,3], kappa[N], alpha[N]
    const float* q     = (const float*)d_in[0];
    const float* r     = (const float*)d_in[1];
    const float* u     = (const float*)d_in[4];
    const float* kappa = (const float*)d_in[5];
    const float* alpha = (const float*)d_in[6];
    float* out = (float*)d_out;

    dim3 grid1(JBLK, SPLITS);
    ewald_pair_kernel<<<grid1, TPB>>>(q, r, u);
    ewald_reduce_kernel<<<JBLK2, TPB2>>>(q, kappa, alpha, out);
    ewald_final_kernel<<<1, 32>>>(out);
}

// round 2
// speedup vs baseline: 1.1741x; 1.1741x over previous
#include <cuda_runtime.h>

#define NP      3072
#define SPLITS  37
#define CHUNK   84              // 37*84 = 3108 >= 3072 (padded)
#define TPB     128
#define JBLK    (NP / TPB)      // 24  -> grid = 24*37 = 888 = 6*148 blocks
#define TPB2    128
#define JBLK2   (NP / TPB2)     // 24

// constants (sigma = 1, A = 1/sqrt(2), A^2 = 1/2)
#define A_CONST 0.7071067811865476f
#define C1      0.7978845608028654f     // 2A/sqrt(pi) == 4A^3/sqrt(pi) since A^2=1/2
#define NC      14.399645f              // 90.4756 / (2*pi)

// Abramowitz-Stegun 7.1.26 erfc coefficients (|err| <= 1.5e-7, x >= 0)
#define P_AS  0.3275911f
#define AS1   0.254829592f
#define AS2  -0.284496736f
#define AS3   1.421413741f
#define AS4  -1.453152027f
#define AS5   1.061405429f

__device__ float g_part[SPLITS * 6 * NP];
__device__ float g_potblk[JBLK2];

__device__ __forceinline__ float rcp_fast(float x) {
    float y;
    asm("rcp.approx.f32 %0, %1;" : "=f"(y) : "f"(x));
    return y;
}

__global__ __launch_bounds__(TPB)
void ewald_pair_kernel(const float* __restrict__ q,
                       const float* __restrict__ r,
                       const float* __restrict__ u)
{
    const int j  = blockIdx.x * TPB + threadIdx.x;
    const int s  = blockIdx.y;
    const int i0 = s * CHUNK;

    __shared__ float4 s_a[CHUNK];   // rx, ry, rz, q
    __shared__ float4 s_b[CHUNK];   // ux, uy, uz, 0

    for (int t = threadIdx.x; t < CHUNK; t += TPB) {
        const int ig = i0 + t;
        float4 av, bv;
        if (ig < NP) {
            av = make_float4(r[3 * ig + 0], r[3 * ig + 1], r[3 * ig + 2], q[ig]);
            bv = make_float4(u[3 * ig + 0], u[3 * ig + 1], u[3 * ig + 2], 0.f);
        } else {
            // padded particle far away with q=0, u=0 -> all contributions exactly 0
            av = make_float4(1e4f, 1e4f, 1e4f, 0.f);
            bv = make_float4(0.f, 0.f, 0.f, 0.f);
        }
        s_a[t] = av;
        s_b[t] = bv;
    }
    __syncthreads();

    const float rjx = r[3 * j + 0];
    const float rjy = r[3 * j + 1];
    const float rjz = r[3 * j + 2];
    const float ujx = u[3 * j + 0];
    const float ujy = u[3 * j + 1];
    const float ujz = u[3 * j + 2];

    float a1 = 0.f, a2 = 0.f, fx = 0.f, fy = 0.f, fz = 0.f, dd = 0.f;

#pragma unroll 4
    for (int t = 0; t < CHUNK; ++t) {
        const float4 a = s_a[t];
        const float4 b = s_b[t];

        const float dx = rjx - a.x;
        const float dy = rjy - a.y;
        const float dz = rjz - a.z;
        const float d2 = fmaf(dx, dx, fmaf(dy, dy, dz * dz));

        // self pair <=> d2 == 0 exactly (positions are distinct random floats)
        const float m   = (d2 != 0.0f) ? 1.0f : 0.0f;
        const float d2s = fmaxf(d2, 1e-12f);

        const float rinv  = rsqrtf(d2s);
        const float g     = __expf(-0.5f * d2s) * m;      // exp(-(A*r)^2), A^2=1/2, masked
        const float rn    = d2s * rinv;
        const float x     = A_CONST * rn;
        const float t1    = rcp_fast(fmaf(P_AS, x, 1.0f));
        const float poly  = fmaf(fmaf(fmaf(fmaf(AS5, t1, AS4), t1, AS3), t1, AS2), t1, AS1);
        const float erfc  = g * t1 * poly;                // masked via g
        const float rinvm = rinv * m;
        const float erinv = fmaf(-erfc, rinvm, rinvm);    // erf(A r)/r, 0 on self
        const float rinv2 = rinv * rinv;
        const float c1g   = C1 * g;
        const float s1    = (erinv - c1g) * rinv2;        // erf*rinv^3 - c1*g*rinv^2
        const float s2v   = fmaf(3.f, s1, -c1g);          // s2 = 3*s1 - C3*g, C3==C1

        a1 = fmaf(a.w, erinv, a1);

        const float uri = fmaf(b.x, dx, fmaf(b.y, dy, b.z * dz));
        a2 = fmaf(s1, uri, a2);

        const float urj = fmaf(ujx, dx, fmaf(ujy, dy, ujz * dz));
        const float uu  = fmaf(b.x, ujx, fmaf(b.y, ujy, b.z * ujz));
        const float s2r = s2v * uri * rinv2;
        dd = fmaf(s2r, urj, dd);
        dd = fmaf(-s1, uu, dd);

        const float tc = fmaf(a.w, s1, s2r);
        fx = fmaf(tc, dx, fx); fx = fmaf(-s1, b.x, fx);
        fy = fmaf(tc, dy, fy); fy = fmaf(-s1, b.y, fy);
        fz = fmaf(tc, dz, fz); fz = fmaf(-s1, b.z, fz);
    }

    float* p = g_part + (size_t)s * 6 * NP;
    p[0 * NP + j] = a1;
    p[1 * NP + j] = a2;
    p[2 * NP + j] = fx;
    p[3 * NP + j] = fy;
    p[4 * NP + j] = fz;
    p[5 * NP + j] = dd;
}

__global__ __launch_bounds__(TPB2)
void ewald_reduce_kernel(const float* __restrict__ q,
                         const float* __restrict__ kappa,
                         const float* __restrict__ alpha,
                         float* __restrict__ out)
{
    const int j = blockIdx.x * TPB2 + threadIdx.x;

    float a1 = 0.f, a2 = 0.f, fx = 0.f, fy = 0.f, fz = 0.f, dd = 0.f;
#pragma unroll
    for (int s = 0; s < SPLITS; ++s) {
        const float* p = g_part + (size_t)s * 6 * NP;
        a1 += p[0 * NP + j];
        a2 += p[1 * NP + j];
        fx += p[2 * NP + j];
        fy += p[3 * NP + j];
        fz += p[4 * NP + j];
        dd += p[5 * NP + j];
    }

    const float ka = kappa[j];
    const float al = alpha[j];
    const float qj = q[j];

    const float ephi = NC * (a1 + a2);
    const float qind = -ka * ephi;
    const float efx = NC * fx, efy = NC * fy, efz = NC * fz;

    out[1 + j] = qind;
    out[1 + NP + 3 * j + 0] = al * efx;
    out[1 + NP + 3 * j + 1] = al * efy;
    out[1 + NP + 3 * j + 2] = al * efz;

    float potj = qj * NC * (0.5f * a1 + a2)
               - 0.5f * NC * dd
               - 0.5f * ka * ephi * ephi
               - 0.5f * al * (efx * efx + efy * efy + efz * efz);

    __shared__ float sh[TPB2];
    sh[threadIdx.x] = potj;
    __syncthreads();
#pragma unroll
    for (int ofs = TPB2 / 2; ofs > 0; ofs >>= 1) {
        if (threadIdx.x < ofs) sh[threadIdx.x] += sh[threadIdx.x + ofs];
        __syncthreads();
    }
    if (threadIdx.x == 0) g_potblk[blockIdx.x] = sh[0];
}

__global__ void ewald_final_kernel(float* __restrict__ out)
{
    double v = 0.0;
    if (threadIdx.x < JBLK2) v = (double)g_potblk[threadIdx.x];
#pragma unroll
    for (int ofs = 16; ofs > 0; ofs >>= 1)
        v += __shfl_down_sync(0xFFFFFFFFu, v, ofs);
    if (threadIdx.x == 0) out[0] = (float)v;
}

extern "C" void kernel_launch(void* const* d_in, const int* in_sizes, int n_in,
                              void* d_out, int out_size)
{
    const float* q     = (const float*)d_in[0];
    const float* r     = (const float*)d_in[1];
    const float* u     = (const float*)d_in[4];
    const float* kappa = (const float*)d_in[5];
    const float* alpha = (const float*)d_in[6];
    float* out = (float*)d_out;

    dim3 grid1(JBLK, SPLITS);
    ewald_pair_kernel<<<grid1, TPB>>>(q, r, u);
    ewald_reduce_kernel<<<JBLK2, TPB2>>>(q, kappa, alpha, out);
    ewald_final_kernel<<<1, 32>>>(out);
}

// round 3
// speedup vs baseline: 1.3174x; 1.1221x over previous
#include <cuda_runtime.h>

#define NP      3072
#define SPLITS  37
#define CHUNK   84              // 37*84 = 3108 >= 3072 (padded)
#define HC      (CHUNK / 2)     // 42 packed iterations
#define TPB     128
#define JBLK    (NP / TPB)      // 24 -> grid = 24*37 = 888 = 6*148 blocks
#define TPB2    64
#define JBLK2   (NP / TPB2)     // 48

// constants (sigma = 1, A = 1/sqrt(2), A^2 = 1/2)
#define A_CONST 0.7071067811865476f
#define C1      0.7978845608028654f     // 2A/sqrt(pi) == 4A^3/sqrt(pi) since A^2=1/2
#define NC      14.399645f              // 90.4756 / (2*pi)
// Abramowitz-Stegun 7.1.26 erfc (|err|<=1.5e-7):  erfc(x) = g*t*P(t), t=1/(1+p*x)
#define P_AS  0.3275911f
#define PA    (P_AS * A_CONST)          // folded: t = 1/(1 + P*A*rn)
#define AS1   0.254829592f
#define AS2  -0.284496736f
#define AS3   1.421413741f
#define AS4  -1.453152027f
#define AS5   1.061405429f
#define L2E   1.4426950408889634f       // log2(e)

typedef unsigned long long u64;

__device__ float g_part[SPLITS * 6 * NP];
__device__ float g_potblk[JBLK2];

__device__ __forceinline__ float rcp_fast(float x) {
    float y; asm("rcp.approx.f32 %0, %1;" : "=f"(y) : "f"(x)); return y;
}
__device__ __forceinline__ u64 pk(float lo, float hi) {
    u64 r; asm("mov.b64 %0, {%1, %2};" : "=l"(r) : "f"(lo), "f"(hi)); return r;
}
__device__ __forceinline__ void upk(u64 a, float& lo, float& hi) {
    asm("mov.b64 {%0, %1}, %2;" : "=f"(lo), "=f"(hi) : "l"(a));
}
__device__ __forceinline__ u64 fma2(u64 a, u64 b, u64 c) {
    u64 d; asm("fma.rn.f32x2 %0, %1, %2, %3;" : "=l"(d) : "l"(a), "l"(b), "l"(c)); return d;
}
__device__ __forceinline__ u64 mul2(u64 a, u64 b) {
    u64 d; asm("mul.rn.f32x2 %0, %1, %2;" : "=l"(d) : "l"(a), "l"(b)); return d;
}
__device__ __forceinline__ u64 add2(u64 a, u64 b) {
    u64 d; asm("add.rn.f32x2 %0, %1, %2;" : "=l"(d) : "l"(a), "l"(b)); return d;
}

__global__ __launch_bounds__(TPB, 6)
void ewald_pair_kernel(const float* __restrict__ q,
                       const float* __restrict__ r,
                       const float* __restrict__ u)
{
    const int j  = blockIdx.x * TPB + threadIdx.x;
    const int s  = blockIdx.y;
    const int i0 = s * CHUNK;

    // packed SoA: element t pairs particles (i0+t) and (i0+t+HC)
    __shared__ ulonglong2 s_p0[HC];   // {-rx2, -ry2}
    __shared__ ulonglong2 s_p1[HC];   // {-rz2,   q2}
    __shared__ ulonglong2 s_p2[HC];   // { ux2,  uy2}
    __shared__ u64        s_p3[HC];   // { uz2 }

    for (int t = threadIdx.x; t < HC; t += TPB) {
        const int ia = i0 + t;
        const int ib = ia + HC;
        float rxa, rya, rza, qa, uxa, uya, uza;
        float rxb, ryb, rzb, qb, uxb, uyb, uzb;
        if (ia < NP) {
            rxa = r[3*ia+0]; rya = r[3*ia+1]; rza = r[3*ia+2];
            qa = q[ia]; uxa = u[3*ia+0]; uya = u[3*ia+1]; uza = u[3*ia+2];
        } else { rxa=1e4f; rya=1e4f; rza=1e4f; qa=0.f; uxa=0.f; uya=0.f; uza=0.f; }
        if (ib < NP) {
            rxb = r[3*ib+0]; ryb = r[3*ib+1]; rzb = r[3*ib+2];
            qb = q[ib]; uxb = u[3*ib+0]; uyb = u[3*ib+1]; uzb = u[3*ib+2];
        } else { rxb=1e4f; ryb=1e4f; rzb=1e4f; qb=0.f; uxb=0.f; uyb=0.f; uzb=0.f; }
        s_p0[t] = make_ulonglong2(pk(-rxa, -rxb), pk(-rya, -ryb));
        s_p1[t] = make_ulonglong2(pk(-rza, -rzb), pk(qa, qb));
        s_p2[t] = make_ulonglong2(pk(uxa, uxb), pk(uya, uyb));
        s_p3[t] = pk(uza, uzb);
    }
    __syncthreads();

    const float rjx = r[3*j+0], rjy = r[3*j+1], rjz = r[3*j+2];
    const float ujx = u[3*j+0], ujy = u[3*j+1], ujz = u[3*j+2];

    const u64 rjx2 = pk(rjx, rjx), rjy2 = pk(rjy, rjy), rjz2 = pk(rjz, rjz);
    // packed constants (negated AS poly so 1-erfc needs no subtract)
    const u64 kNA5 = pk(-AS5, -AS5), kNA4 = pk(-AS4, -AS4), kNA3 = pk(-AS3, -AS3);
    const u64 kNA2 = pk(-AS2, -AS2), kNA1 = pk(-AS1, -AS1);
    const u64 kOne = 0x3f8000003f800000ull;
    const u64 kNC1 = pk(-C1, -C1);
    const u64 kThree = 0x4040000040400000ull;

    u64 a1 = 0, a2 = 0;
    u64 hx = 0, hy = 0, hz = 0;   // sum s2r * d
    u64 wx = 0, wy = 0, wz = 0;   // sum q*s1 * d
    u64 gx = 0, gy = 0, gz = 0;   // sum s1 * u_i

#pragma unroll 3
    for (int t = 0; t < HC; ++t) {
        const ulonglong2 p0 = s_p0[t];
        const ulonglong2 p1 = s_p1[t];
        const ulonglong2 p2 = s_p2[t];
        const u64 uz2 = s_p3[t];

        const u64 dx = add2(rjx2, p0.x);
        const u64 dy = add2(rjy2, p0.y);
        const u64 dz = add2(rjz2, p1.x);
        u64 d2 = mul2(dx, dx);
        d2 = fma2(dy, dy, d2);
        d2 = fma2(dz, dz, d2);

        // scalar section: mask + MUFU per half
        float d2l, d2h; upk(d2, d2l, d2h);
        d2l = (d2l == 0.f) ? 1e30f : d2l;       // self -> huge distance
        d2h = (d2h == 0.f) ? 1e30f : d2h;
        const float rl = rsqrtf(d2l), rh = rsqrtf(d2h);
        float gl, gh;
        asm("ex2.approx.f32 %0, %1;" : "=f"(gl) : "f"(-0.5f * L2E * d2l));
        asm("ex2.approx.f32 %0, %1;" : "=f"(gh) : "f"(-0.5f * L2E * d2h));
        const float rnl = d2l * rl, rnh = d2h * rh;         // |r|
        const float tl = rcp_fast(fmaf(PA, rnl, 1.0f));
        const float th = rcp_fast(fmaf(PA, rnh, 1.0f));
        const u64 rinv = pk(rl, rh);
        const u64 gg   = pk(gl, gh);
        const u64 tt   = pk(tl, th);

        // erf(A r)/r = (1 - erfc) * rinv
        u64 np = fma2(kNA5, tt, kNA4);
        np = fma2(np, tt, kNA3);
        np = fma2(np, tt, kNA2);
        np = fma2(np, tt, kNA1);
        const u64 gt    = mul2(gg, tt);
        const u64 om    = fma2(gt, np, kOne);
        const u64 erinv = mul2(om, rinv);
        const u64 rr    = mul2(rinv, rinv);
        const u64 ng    = mul2(gg, kNC1);                    // -C1*g
        const u64 s1    = mul2(add2(erinv, ng), rr);
        const u64 s2v   = fma2(kThree, s1, ng);

        a1 = fma2(p1.y, erinv, a1);

        u64 uri = mul2(p2.x, dx);
        uri = fma2(p2.y, dy, uri);
        uri = fma2(uz2, dz, uri);
        a2 = fma2(s1, uri, a2);

        const u64 s2r = mul2(mul2(s2v, uri), rr);
        hx = fma2(s2r, dx, hx);
        hy = fma2(s2r, dy, hy);
        hz = fma2(s2r, dz, hz);
        const u64 qs1 = mul2(p1.y, s1);
        wx = fma2(qs1, dx, wx);
        wy = fma2(qs1, dy, wy);
        wz = fma2(qs1, dz, wz);
        gx = fma2(s1, p2.x, gx);
        gy = fma2(s1, p2.y, gy);
        gz = fma2(s1, uz2, gz);
    }

    // combine packed halves
    float l, h;
    upk(a1, l, h); const float A1 = l + h;
    upk(a2, l, h); const float A2 = l + h;
    upk(hx, l, h); float Hx = l + h;
    upk(hy, l, h); float Hy = l + h;
    upk(hz, l, h); float Hz = l + h;
    upk(wx, l, h); const float Wx = l + h;
    upk(wy, l, h); const float Wy = l + h;
    upk(wz, l, h); const float Wz = l + h;
    upk(gx, l, h); const float Gx = l + h;
    upk(gy, l, h); const float Gy = l + h;
    upk(gz, l, h); const float Gz = l + h;

    const float Mx = Hx - Gx, My = Hy - Gy, Mz = Hz - Gz;   // m = h - g
    const float fx = Wx + Mx, fy = Wy + My, fz = Wz + Mz;   // E-field pre-NC
    const float dd = ujx * Mx + ujy * My + ujz * Mz;        // dipole-dipole scalar

    float* p = g_part + (size_t)s * 6 * NP;
    p[0*NP + j] = A1;
    p[1*NP + j] = A2;
    p[2*NP + j] = fx;
    p[3*NP + j] = fy;
    p[4*NP + j] = fz;
    p[5*NP + j] = dd;
}

__global__ __launch_bounds__(TPB2)
void ewald_reduce_kernel(const float* __restrict__ q,
                         const float* __restrict__ kappa,
                         const float* __restrict__ alpha,
                         float* __restrict__ out)
{
    const int j = blockIdx.x * TPB2 + threadIdx.x;

    float a1 = 0.f, a2 = 0.f, fx = 0.f, fy = 0.f, fz = 0.f, dd = 0.f;
#pragma unroll
    for (int s = 0; s < SPLITS; ++s) {
        const float* p = g_part + (size_t)s * 6 * NP;
        a1 += p[0*NP + j];
        a2 += p[1*NP + j];
        fx += p[2*NP + j];
        fy += p[3*NP + j];
        fz += p[4*NP + j];
        dd += p[5*NP + j];
    }

    const float ka = kappa[j];
    const float al = alpha[j];
    const float qj = q[j];

    const float ephi = NC * (a1 + a2);
    const float qind = -ka * ephi;
    const float efx = NC * fx, efy = NC * fy, efz = NC * fz;

    out[1 + j] = qind;
    out[1 + NP + 3*j + 0] = al * efx;
    out[1 + NP + 3*j + 1] = al * efy;
    out[1 + NP + 3*j + 2] = al * efz;

    float potj = qj * NC * (0.5f * a1 + a2)
               - 0.5f * NC * dd
               - 0.5f * ka * ephi * ephi
               - 0.5f * al * (efx * efx + efy * efy + efz * efz);

    __shared__ float sh[TPB2];
    sh[threadIdx.x] = potj;
    __syncthreads();
#pragma unroll
    for (int ofs = TPB2 / 2; ofs > 0; ofs >>= 1) {
        if (threadIdx.x < ofs) sh[threadIdx.x] += sh[threadIdx.x + ofs];
        __syncthreads();
    }
    if (threadIdx.x == 0) g_potblk[blockIdx.x] = sh[0];
}

__global__ void ewald_final_kernel(float* __restrict__ out)
{
    double v = 0.0;
    const int lid = threadIdx.x;
    if (lid < 32) {
        v = (double)g_potblk[lid];
        if (lid + 32 < JBLK2) v += (double)g_potblk[lid + 32];
    }
#pragma unroll
    for (int ofs = 16; ofs > 0; ofs >>= 1)
        v += __shfl_down_sync(0xFFFFFFFFu, v, ofs);
    if (lid == 0) out[0] = (float)v;
}

extern "C" void kernel_launch(void* const* d_in, const int* in_sizes, int n_in,
                              void* d_out, int out_size)
{
    const float* q     = (const float*)d_in[0];
    const float* r     = (const float*)d_in[1];
    const float* u     = (const float*)d_in[4];
    const float* kappa = (const float*)d_in[5];
    const float* alpha = (const float*)d_in[6];
    float* out = (float*)d_out;

    dim3 grid1(JBLK, SPLITS);
    ewald_pair_kernel<<<grid1, TPB>>>(q, r, u);
    ewald_reduce_kernel<<<JBLK2, TPB2>>>(q, kappa, alpha, out);
    ewald_final_kernel<<<1, 32>>>(out);
}

// round 4
// speedup vs baseline: 1.5289x; 1.1606x over previous
#include <cuda_runtime.h>

#define NP      3072
#define SPLITS  37
#define CHUNK   84              // 37*84 = 3108 >= 3072 (padded)
#define HC      (CHUNK / 2)     // 42 packed iterations
#define TPB     128
#define JBLK    (NP / TPB)      // 24 -> grid = 24*37 = 888 = 6*148 blocks
#define TPB2    64
#define JBLK2   (NP / TPB2)     // 48

// constants (sigma = 1, A = 1/sqrt(2), A^2 = 1/2)
#define A_CONST 0.7071067811865476f
#define C1      0.7978845608028654f     // 2A/sqrt(pi) == 4A^3/sqrt(pi) since A^2=1/2
#define NC      14.399645f              // 90.4756 / (2*pi)
// Abramowitz-Stegun 7.1.26 erfc: erfc(x) = g*t*P(t), t=1/(1+p*x), |err|<=1.5e-7
#define P_AS  0.3275911f
#define PA    (P_AS * A_CONST)
#define AS1   0.254829592f
#define AS2  -0.284496736f
#define AS3   1.421413741f
#define AS4  -1.453152027f
#define AS5   1.061405429f
#define NL2E_HALF (-0.7213475204444817f)  // -0.5*log2(e)
#define RCUT2     20.25f                   // beyond this erf=1,g=0 to ~1e-4 rel
#define RINV_CUT  0.2222f                  // 1/sqrt(RCUT2)

typedef unsigned long long u64;

__device__ float g_part[SPLITS * 6 * NP];
__device__ float g_potblk[JBLK2];
__device__ int   g_sem;

__device__ __forceinline__ float rcp_fast(float x) {
    float y; asm("rcp.approx.f32 %0, %1;" : "=f"(y) : "f"(x)); return y;
}
__device__ __forceinline__ float ex2_fast(float x) {
    float y; asm("ex2.approx.f32 %0, %1;" : "=f"(y) : "f"(x)); return y;
}
__device__ __forceinline__ u64 pk(float lo, float hi) {
    u64 r; asm("mov.b64 %0, {%1, %2};" : "=l"(r) : "f"(lo), "f"(hi)); return r;
}
__device__ __forceinline__ void upk(u64 a, float& lo, float& hi) {
    asm("mov.b64 {%0, %1}, %2;" : "=f"(lo), "=f"(hi) : "l"(a));
}
__device__ __forceinline__ u64 fma2(u64 a, u64 b, u64 c) {
    u64 d; asm("fma.rn.f32x2 %0, %1, %2, %3;" : "=l"(d) : "l"(a), "l"(b), "l"(c)); return d;
}
__device__ __forceinline__ u64 mul2(u64 a, u64 b) {
    u64 d; asm("mul.rn.f32x2 %0, %1, %2;" : "=l"(d) : "l"(a), "l"(b)); return d;
}
__device__ __forceinline__ u64 add2(u64 a, u64 b) {
    u64 d; asm("add.rn.f32x2 %0, %1, %2;" : "=l"(d) : "l"(a), "l"(b)); return d;
}

// scalar correction for one near pair: add (true - bare) terms; everything ~ g
__device__ __forceinline__ void corr_half(
    float dx, float dy, float dz, float qi,
    float ux, float uy, float uz, bool act,
    float& A1, float& A2,
    float& Hx, float& Hy, float& Hz,
    float& Wx, float& Wy, float& Wz,
    float& Gx, float& Gy, float& Gz)
{
    // recompute d2 with the SAME op order as pass A (mul, fma, fma)
    float t0 = dx * dx;
    t0 = fmaf(dy, dy, t0);
    const float d2 = fmaf(dz, dz, t0);
    const bool on = act && (d2 != 0.f) && (d2 < RCUT2);
    const float d2s  = fmaxf(d2, 1e-8f);
    const float rinv = rsqrtf(d2s);
    const float m    = on ? 1.f : 0.f;
    const float g    = ex2_fast(NL2E_HALF * d2s) * m;  // masks ALL corrections
    const float rn   = d2s * rinv;
    const float tt   = rcp_fast(fmaf(PA, rn, 1.f));
    const float poly = fmaf(fmaf(fmaf(fmaf(AS5, tt, AS4), tt, AS3), tt, AS2), tt, AS1);
    const float erfc = g * tt * poly;
    const float de   = -erfc * rinv;                   // delta erinv
    const float rr   = rinv * rinv;
    const float c1g  = C1 * g;
    const float ds1  = (de - c1g) * rr;                // delta s1
    const float uri  = fmaf(ux, dx, fmaf(uy, dy, uz * dz));
    const float ds2r = fmaf(3.f, ds1, -c1g) * (uri * rr);
    A1 = fmaf(qi, de, A1);
    A2 = fmaf(ds1, uri, A2);
    Hx = fmaf(ds2r, dx, Hx); Hy = fmaf(ds2r, dy, Hy); Hz = fmaf(ds2r, dz, Hz);
    const float qd = qi * ds1;
    Wx = fmaf(qd, dx, Wx); Wy = fmaf(qd, dy, Wy); Wz = fmaf(qd, dz, Wz);
    Gx = fmaf(ds1, ux, Gx); Gy = fmaf(ds1, uy, Gy); Gz = fmaf(ds1, uz, Gz);
}

__global__ __launch_bounds__(TPB, 6)
void ewald_pair_kernel(const float* __restrict__ q,
                       const float* __restrict__ r,
                       const float* __restrict__ u)
{
    const int j  = blockIdx.x * TPB + threadIdx.x;
    const int s  = blockIdx.y;
    const int i0 = s * CHUNK;

    __shared__ ulonglong2 s_p0[HC];   // {-rx2, -ry2}
    __shared__ ulonglong2 s_p1[HC];   // {-rz2,   q2}
    __shared__ ulonglong2 s_p2[HC];   // { ux2,  uy2}
    __shared__ u64        s_p3[HC];   // { uz2 }

    for (int t = threadIdx.x; t < HC; t += TPB) {
        const int ia = i0 + t;
        const int ib = ia + HC;
        float rxa, rya, rza, qa, uxa, uya, uza;
        float rxb, ryb, rzb, qb, uxb, uyb, uzb;
        if (ia < NP) {
            rxa = r[3*ia+0]; rya = r[3*ia+1]; rza = r[3*ia+2];
            qa = q[ia]; uxa = u[3*ia+0]; uya = u[3*ia+1]; uza = u[3*ia+2];
        } else { rxa=1e4f; rya=1e4f; rza=1e4f; qa=0.f; uxa=0.f; uya=0.f; uza=0.f; }
        if (ib < NP) {
            rxb = r[3*ib+0]; ryb = r[3*ib+1]; rzb = r[3*ib+2];
            qb = q[ib]; uxb = u[3*ib+0]; uyb = u[3*ib+1]; uzb = u[3*ib+2];
        } else { rxb=1e4f; ryb=1e4f; rzb=1e4f; qb=0.f; uxb=0.f; uyb=0.f; uzb=0.f; }
        s_p0[t] = make_ulonglong2(pk(-rxa, -rxb), pk(-rya, -ryb));
        s_p1[t] = make_ulonglong2(pk(-rza, -rzb), pk(qa, qb));
        s_p2[t] = make_ulonglong2(pk(uxa, uxb), pk(uya, uyb));
        s_p3[t] = pk(uza, uzb);
    }
    __syncthreads();

    const float rjx = r[3*j+0], rjy = r[3*j+1], rjz = r[3*j+2];
    const float ujx = u[3*j+0], ujy = u[3*j+1], ujz = u[3*j+2];

    const u64 rjx2 = pk(rjx, rjx), rjy2 = pk(rjy, rjy), rjz2 = pk(rjz, rjz);
    const u64 kThree = 0x4040000040400000ull;

    u64 a1 = 0, a2 = 0;
    u64 hx = 0, hy = 0, hz = 0;   // sum s2r * d  (bare: 3*uri*rinv^5 * d)
    u64 wx = 0, wy = 0, wz = 0;   // sum q*s1 * d
    u64 gx = 0, gy = 0, gz = 0;   // sum s1 * u_i
    u64 mask = 0;

    // ---------------- Pass A: bare Coulomb (erf=1, g=0) for ALL pairs ----------------
#pragma unroll 6
    for (int t = 0; t < HC; ++t) {
        const ulonglong2 p0 = s_p0[t];
        const ulonglong2 p1 = s_p1[t];
        const ulonglong2 p2 = s_p2[t];
        const u64 uz2 = s_p3[t];

        const u64 dx = add2(rjx2, p0.x);
        const u64 dy = add2(rjy2, p0.y);
        const u64 dz = add2(rjz2, p1.x);
        u64 d2 = mul2(dx, dx);
        d2 = fma2(dy, dy, d2);
        d2 = fma2(dz, dz, d2);

        float d2l, d2h; upk(d2, d2l, d2h);
        float rl = rsqrtf(d2l), rh = rsqrtf(d2h);
        rl = (d2l == 0.f) ? 0.f : rl;          // self pair -> contributes exactly 0
        rh = (d2h == 0.f) ? 0.f : rh;
        // near pair (either half): rinv > 1/4.5 (self excluded since rinv=0)
        const bool near = fmaxf(rl, rh) > RINV_CUT;
        mask |= ((u64)near) << t;

        const u64 rinv = pk(rl, rh);
        const u64 rr   = mul2(rinv, rinv);
        const u64 s1   = mul2(rinv, rr);       // bare s1 = rinv^3 (erinv = rinv)

        a1 = fma2(p1.y, rinv, a1);

        u64 uri = mul2(p2.x, dx);
        uri = fma2(p2.y, dy, uri);
        uri = fma2(uz2, dz, uri);
        a2 = fma2(s1, uri, a2);

        const u64 v   = mul2(uri, rr);
        const u64 v3  = mul2(v, kThree);
        const u64 s2r = mul2(s1, v3);          // 3*s1*uri*rinv^2

        hx = fma2(s2r, dx, hx);
        hy = fma2(s2r, dy, hy);
        hz = fma2(s2r, dz, hz);
        const u64 qs1 = mul2(p1.y, s1);
        wx = fma2(qs1, dx, wx);
        wy = fma2(qs1, dy, wy);
        wz = fma2(qs1, dz, wz);
        gx = fma2(s1, p2.x, gx);
        gy = fma2(s1, p2.y, gy);
        gz = fma2(s1, uz2, gz);
    }

    // combine packed halves into scalars
    float l, h;
    upk(a1, l, h); float A1 = l + h;
    upk(a2, l, h); float A2 = l + h;
    upk(hx, l, h); float Hx = l + h;
    upk(hy, l, h); float Hy = l + h;
    upk(hz, l, h); float Hz = l + h;
    upk(wx, l, h); float Wx = l + h;
    upk(wy, l, h); float Wy = l + h;
    upk(wz, l, h); float Wz = l + h;
    upk(gx, l, h); float Gx = l + h;
    upk(gy, l, h); float Gy = l + h;
    upk(gz, l, h); float Gz = l + h;

    // ---------------- Pass B: sparse erf/gauss corrections for near pairs ----------------
    unsigned mlo = (unsigned)mask;
    unsigned mhi = (unsigned)(mask >> 32);
    while (__any_sync(0xFFFFFFFFu, mlo | mhi)) {
        const bool act = (mlo | mhi) != 0u;
        int t = 0;
        if (mlo) { t = __ffs(mlo) - 1;  mlo &= mlo - 1u; }
        else if (mhi) { t = __ffs(mhi) + 31; mhi &= mhi - 1u; }

        const ulonglong2 p0 = s_p0[t];
        const ulonglong2 p1 = s_p1[t];
        const ulonglong2 p2 = s_p2[t];
        const u64 uz2 = s_p3[t];
        float nrxl, nrxh, nryl, nryh, nrzl, nrzh, ql, qh;
        float uxl, uxh, uyl, uyh, uzl, uzh;
        upk(p0.x, nrxl, nrxh); upk(p0.y, nryl, nryh);
        upk(p1.x, nrzl, nrzh); upk(p1.y, ql, qh);
        upk(p2.x, uxl, uxh);   upk(p2.y, uyl, uyh);
        upk(uz2, uzl, uzh);

        corr_half(rjx + nrxl, rjy + nryl, rjz + nrzl, ql, uxl, uyl, uzl, act,
                  A1, A2, Hx, Hy, Hz, Wx, Wy, Wz, Gx, Gy, Gz);
        corr_half(rjx + nrxh, rjy + nryh, rjz + nrzh, qh, uxh, uyh, uzh, act,
                  A1, A2, Hx, Hy, Hz, Wx, Wy, Wz, Gx, Gy, Gz);
    }

    const float Mx = Hx - Gx, My = Hy - Gy, Mz = Hz - Gz;
    const float fx = Wx + Mx, fy = Wy + My, fz = Wz + Mz;       // E-field pre-NC
    const float dd = ujx * Mx + ujy * My + ujz * Mz;            // dipole-dipole scalar

    float* p = g_part + (size_t)s * 6 * NP;
    p[0*NP + j] = A1;
    p[1*NP + j] = A2;
    p[2*NP + j] = fx;
    p[3*NP + j] = fy;
    p[4*NP + j] = fz;
    p[5*NP + j] = dd;
}

__global__ __launch_bounds__(TPB2)
void ewald_reduce_kernel(const float* __restrict__ q,
                         const float* __restrict__ kappa,
                         const float* __restrict__ alpha,
                         float* __restrict__ out)
{
    const int j = blockIdx.x * TPB2 + threadIdx.x;

    float a1 = 0.f, a2 = 0.f, fx = 0.f, fy = 0.f, fz = 0.f, dd = 0.f;
#pragma unroll
    for (int s = 0; s < SPLITS; ++s) {
        const float* p = g_part + (size_t)s * 6 * NP;
        a1 += p[0*NP + j];
        a2 += p[1*NP + j];
        fx += p[2*NP + j];
        fy += p[3*NP + j];
        fz += p[4*NP + j];
        dd += p[5*NP + j];
    }

    const float ka = kappa[j];
    const float al = alpha[j];
    const float qj = q[j];

    const float ephi = NC * (a1 + a2);
    const float qind = -ka * ephi;
    const float efx = NC * fx, efy = NC * fy, efz = NC * fz;

    out[1 + j] = qind;
    out[1 + NP + 3*j + 0] = al * efx;
    out[1 + NP + 3*j + 1] = al * efy;
    out[1 + NP + 3*j + 2] = al * efz;

    float potj = qj * NC * (0.5f * a1 + a2)
               - 0.5f * NC * dd
               - 0.5f * ka * ephi * ephi
               - 0.5f * al * (efx * efx + efy * efy + efz * efz);

    __shared__ float sh[TPB2];
    __shared__ bool  lastblk;
    sh[threadIdx.x] = potj;
    __syncthreads();
#pragma unroll
    for (int ofs = TPB2 / 2; ofs > 0; ofs >>= 1) {
        if (threadIdx.x < ofs) sh[threadIdx.x] += sh[threadIdx.x + ofs];
        __syncthreads();
    }
    if (threadIdx.x == 0) {
        g_potblk[blockIdx.x] = sh[0];
        __threadfence();
        const int old = atomicAdd(&g_sem, 1);
        lastblk = (old == JBLK2 - 1);
    }
    __syncthreads();

    if (lastblk) {
        __threadfence();
        float v = (threadIdx.x < JBLK2) ? g_potblk[threadIdx.x] : 0.f;
        sh[threadIdx.x] = v;
        __syncthreads();
#pragma unroll
        for (int ofs = TPB2 / 2; ofs > 0; ofs >>= 1) {
            if (threadIdx.x < ofs) sh[threadIdx.x] += sh[threadIdx.x + ofs];
            __syncthreads();
        }
        if (threadIdx.x == 0) {
            out[0] = sh[0];
            g_sem = 0;    // reset for next graph replay
        }
    }
}

extern "C" void kernel_launch(void* const* d_in, const int* in_sizes, int n_in,
                              void* d_out, int out_size)
{
    const float* q     = (const float*)d_in[0];
    const float* r     = (const float*)d_in[1];
    const float* u     = (const float*)d_in[4];
    const float* kappa = (const float*)d_in[5];
    const float* alpha = (const float*)d_in[6];
    float* out = (float*)d_out;

    dim3 grid1(JBLK, SPLITS);
    ewald_pair_kernel<<<grid1, TPB>>>(q, r, u);
    ewald_reduce_kernel<<<JBLK2, TPB2>>>(q, kappa, alpha, out);
}

// round 5
// speedup vs baseline: 1.6372x; 1.0708x over previous
#include <cuda_runtime.h>

#define NP      3072
#define SPLITS  37
#define CHUNK   84              // 37*84 = 3108 >= 3072 (padded)
#define HC      (CHUNK / 2)     // 42 packed iterations
#define TPB     128
#define JBLK    (NP / TPB)      // 24 -> grid = 24*37 = 888 = 6*148 blocks

#define RJ      32              // j per reduce block
#define RBLK    (NP / RJ)       // 96 reduce blocks
#define TPB2    128             // 4 warps: 4 split-slices of one 32-j group
#define SSLICE  10              // ceil(37/4)

// constants (sigma = 1, A = 1/sqrt(2), A^2 = 1/2)
#define A_CONST 0.7071067811865476f
#define C1      0.7978845608028654f     // 2A/sqrt(pi) == 4A^3/sqrt(pi) since A^2=1/2
#define NC      14.399645f              // 90.4756 / (2*pi)
// Abramowitz-Stegun 7.1.26 erfc: erfc(x) = g*t*P(t), t=1/(1+p*x), |err|<=1.5e-7
#define P_AS  0.3275911f
#define PA    (P_AS * A_CONST)
#define AS1   0.254829592f
#define AS2  -0.284496736f
#define AS3   1.421413741f
#define AS4  -1.453152027f
#define AS5   1.061405429f
#define NL2E_HALF (-0.7213475204444817f)  // -0.5*log2(e)
#define RCUT2     20.25f                   // beyond this erf=1,g=0 to ~1e-4 rel
#define RINV_CUT  0.2222f                  // 1/sqrt(RCUT2)

typedef unsigned long long u64;

__device__ float g_part[SPLITS * 6 * NP];
__device__ float g_potblk[RBLK];
__device__ int   g_sem;

__device__ __forceinline__ float rcp_fast(float x) {
    float y; asm("rcp.approx.f32 %0, %1;" : "=f"(y) : "f"(x)); return y;
}
__device__ __forceinline__ float ex2_fast(float x) {
    float y; asm("ex2.approx.f32 %0, %1;" : "=f"(y) : "f"(x)); return y;
}
__device__ __forceinline__ u64 pk(float lo, float hi) {
    u64 r; asm("mov.b64 %0, {%1, %2};" : "=l"(r) : "f"(lo), "f"(hi)); return r;
}
__device__ __forceinline__ void upk(u64 a, float& lo, float& hi) {
    asm("mov.b64 {%0, %1}, %2;" : "=f"(lo), "=f"(hi) : "l"(a));
}
__device__ __forceinline__ u64 fma2(u64 a, u64 b, u64 c) {
    u64 d; asm("fma.rn.f32x2 %0, %1, %2, %3;" : "=l"(d) : "l"(a), "l"(b), "l"(c)); return d;
}
__device__ __forceinline__ u64 mul2(u64 a, u64 b) {
    u64 d; asm("mul.rn.f32x2 %0, %1, %2;" : "=l"(d) : "l"(a), "l"(b)); return d;
}
__device__ __forceinline__ u64 add2(u64 a, u64 b) {
    u64 d; asm("add.rn.f32x2 %0, %1, %2;" : "=l"(d) : "l"(a), "l"(b)); return d;
}

// scalar correction for one near pair: add (true - bare) terms; everything ~ g
__device__ __forceinline__ void corr_half(
    float dx, float dy, float dz, float qi,
    float ux, float uy, float uz, bool act,
    float& A1, float& A2,
    float& Hx, float& Hy, float& Hz,
    float& Wx, float& Wy, float& Wz,
    float& Gx, float& Gy, float& Gz)
{
    float t0 = dx * dx;
    t0 = fmaf(dy, dy, t0);
    const float d2 = fmaf(dz, dz, t0);
    const bool on = act && (d2 != 0.f) && (d2 < RCUT2);
    const float d2s  = fmaxf(d2, 1e-8f);
    const float rinv = rsqrtf(d2s);
    const float m    = on ? 1.f : 0.f;
    const float g    = ex2_fast(NL2E_HALF * d2s) * m;
    const float rn   = d2s * rinv;
    const float tt   = rcp_fast(fmaf(PA, rn, 1.f));
    const float poly = fmaf(fmaf(fmaf(fmaf(AS5, tt, AS4), tt, AS3), tt, AS2), tt, AS1);
    const float erfc = g * tt * poly;
    const float de   = -erfc * rinv;
    const float rr   = rinv * rinv;
    const float c1g  = C1 * g;
    const float ds1  = (de - c1g) * rr;
    const float uri  = fmaf(ux, dx, fmaf(uy, dy, uz * dz));
    const float ds2r = fmaf(3.f, ds1, -c1g) * (uri * rr);
    A1 = fmaf(qi, de, A1);
    A2 = fmaf(ds1, uri, A2);
    Hx = fmaf(ds2r, dx, Hx); Hy = fmaf(ds2r, dy, Hy); Hz = fmaf(ds2r, dz, Hz);
    const float qd = qi * ds1;
    Wx = fmaf(qd, dx, Wx); Wy = fmaf(qd, dy, Wy); Wz = fmaf(qd, dz, Wz);
    Gx = fmaf(ds1, ux, Gx); Gy = fmaf(ds1, uy, Gy); Gz = fmaf(ds1, uz, Gz);
}

__global__ __launch_bounds__(TPB, 6)
void ewald_pair_kernel(const float* __restrict__ q,
                       const float* __restrict__ r,
                       const float* __restrict__ u)
{
    const int j  = blockIdx.x * TPB + threadIdx.x;
    const int s  = blockIdx.y;
    const int i0 = s * CHUNK;

    __shared__ ulonglong2 s_p0[HC];   // {-rx2, -ry2}
    __shared__ ulonglong2 s_p1[HC];   // {-rz2,   q2}
    __shared__ ulonglong2 s_p2[HC];   // { ux2,  uy2}
    __shared__ u64        s_p3[HC];   // { uz2 }

    for (int t = threadIdx.x; t < HC; t += TPB) {
        const int ia = i0 + t;
        const int ib = ia + HC;
        float rxa, rya, rza, qa, uxa, uya, uza;
        float rxb, ryb, rzb, qb, uxb, uyb, uzb;
        if (ia < NP) {
            rxa = r[3*ia+0]; rya = r[3*ia+1]; rza = r[3*ia+2];
            qa = q[ia]; uxa = u[3*ia+0]; uya = u[3*ia+1]; uza = u[3*ia+2];
        } else { rxa=1e4f; rya=1e4f; rza=1e4f; qa=0.f; uxa=0.f; uya=0.f; uza=0.f; }
        if (ib < NP) {
            rxb = r[3*ib+0]; ryb = r[3*ib+1]; rzb = r[3*ib+2];
            qb = q[ib]; uxb = u[3*ib+0]; uyb = u[3*ib+1]; uzb = u[3*ib+2];
        } else { rxb=1e4f; ryb=1e4f; rzb=1e4f; qb=0.f; uxb=0.f; uyb=0.f; uzb=0.f; }
        s_p0[t] = make_ulonglong2(pk(-rxa, -rxb), pk(-rya, -ryb));
        s_p1[t] = make_ulonglong2(pk(-rza, -rzb), pk(qa, qb));
        s_p2[t] = make_ulonglong2(pk(uxa, uxb), pk(uya, uyb));
        s_p3[t] = pk(uza, uzb);
    }
    __syncthreads();

    const float rjx = r[3*j+0], rjy = r[3*j+1], rjz = r[3*j+2];
    const float ujx = u[3*j+0], ujy = u[3*j+1], ujz = u[3*j+2];

    const u64 rjx2 = pk(rjx, rjx), rjy2 = pk(rjy, rjy), rjz2 = pk(rjz, rjz);
    const u64 kThree = 0x4040000040400000ull;

    u64 a1 = 0, a2 = 0;
    u64 hx = 0, hy = 0, hz = 0;
    u64 wx = 0, wy = 0, wz = 0;
    u64 gx = 0, gy = 0, gz = 0;
    u64 mask = 0;

    // ---------------- Pass A: bare Coulomb (erf=1, g=0) for ALL pairs ----------------
#pragma unroll 6
    for (int t = 0; t < HC; ++t) {
        const ulonglong2 p0 = s_p0[t];
        const ulonglong2 p1 = s_p1[t];
        const ulonglong2 p2 = s_p2[t];
        const u64 uz2 = s_p3[t];

        const u64 dx = add2(rjx2, p0.x);
        const u64 dy = add2(rjy2, p0.y);
        const u64 dz = add2(rjz2, p1.x);
        u64 d2 = mul2(dx, dx);
        d2 = fma2(dy, dy, d2);
        d2 = fma2(dz, dz, d2);

        float d2l, d2h; upk(d2, d2l, d2h);
        float rl = rsqrtf(d2l), rh = rsqrtf(d2h);
        rl = (d2l == 0.f) ? 0.f : rl;
        rh = (d2h == 0.f) ? 0.f : rh;
        const bool near = fmaxf(rl, rh) > RINV_CUT;
        mask |= ((u64)near) << t;

        const u64 rinv = pk(rl, rh);
        const u64 rr   = mul2(rinv, rinv);
        const u64 s1   = mul2(rinv, rr);

        a1 = fma2(p1.y, rinv, a1);

        u64 uri = mul2(p2.x, dx);
        uri = fma2(p2.y, dy, uri);
        uri = fma2(uz2, dz, uri);
        a2 = fma2(s1, uri, a2);

        const u64 v   = mul2(uri, rr);
        const u64 v3  = mul2(v, kThree);
        const u64 s2r = mul2(s1, v3);

        hx = fma2(s2r, dx, hx);
        hy = fma2(s2r, dy, hy);
        hz = fma2(s2r, dz, hz);
        const u64 qs1 = mul2(p1.y, s1);
        wx = fma2(qs1, dx, wx);
        wy = fma2(qs1, dy, wy);
        wz = fma2(qs1, dz, wz);
        gx = fma2(s1, p2.x, gx);
        gy = fma2(s1, p2.y, gy);
        gz = fma2(s1, uz2, gz);
    }

    float l, h;
    upk(a1, l, h); float A1 = l + h;
    upk(a2, l, h); float A2 = l + h;
    upk(hx, l, h); float Hx = l + h;
    upk(hy, l, h); float Hy = l + h;
    upk(hz, l, h); float Hz = l + h;
    upk(wx, l, h); float Wx = l + h;
    upk(wy, l, h); float Wy = l + h;
    upk(wz, l, h); float Wz = l + h;
    upk(gx, l, h); float Gx = l + h;
    upk(gy, l, h); float Gy = l + h;
    upk(gz, l, h); float Gz = l + h;

    // ---------------- Pass B: sparse erf/gauss corrections for near pairs ----------------
    unsigned mlo = (unsigned)mask;
    unsigned mhi = (unsigned)(mask >> 32);
    while (__any_sync(0xFFFFFFFFu, mlo | mhi)) {
        const bool act = (mlo | mhi) != 0u;
        int t = 0;
        if (mlo) { t = __ffs(mlo) - 1;  mlo &= mlo - 1u; }
        else if (mhi) { t = __ffs(mhi) + 31; mhi &= mhi - 1u; }

        const ulonglong2 p0 = s_p0[t];
        const ulonglong2 p1 = s_p1[t];
        const ulonglong2 p2 = s_p2[t];
        const u64 uz2 = s_p3[t];
        float nrxl, nrxh, nryl, nryh, nrzl, nrzh, ql, qh;
        float uxl, uxh, uyl, uyh, uzl, uzh;
        upk(p0.x, nrxl, nrxh); upk(p0.y, nryl, nryh);
        upk(p1.x, nrzl, nrzh); upk(p1.y, ql, qh);
        upk(p2.x, uxl, uxh);   upk(p2.y, uyl, uyh);
        upk(uz2, uzl, uzh);

        corr_half(rjx + nrxl, rjy + nryl, rjz + nrzl, ql, uxl, uyl, uzl, act,
                  A1, A2, Hx, Hy, Hz, Wx, Wy, Wz, Gx, Gy, Gz);
        corr_half(rjx + nrxh, rjy + nryh, rjz + nrzh, qh, uxh, uyh, uzh, act,
                  A1, A2, Hx, Hy, Hz, Wx, Wy, Wz, Gx, Gy, Gz);
    }

    const float Mx = Hx - Gx, My = Hy - Gy, Mz = Hz - Gz;
    const float fx = Wx + Mx, fy = Wy + My, fz = Wz + Mz;
    const float dd = ujx * Mx + ujy * My + ujz * Mz;

    float* p = g_part + (size_t)s * 6 * NP;
    p[0*NP + j] = A1;
    p[1*NP + j] = A2;
    p[2*NP + j] = fx;
    p[3*NP + j] = fy;
    p[4*NP + j] = fz;
    p[5*NP + j] = dd;
}

// 96 blocks x 128 threads: 4 warps each own a ~10-split slice of 32 j's.
__global__ __launch_bounds__(TPB2)
void ewald_reduce_kernel(const float* __restrict__ q,
                         const float* __restrict__ kappa,
                         const float* __restrict__ alpha,
                         float* __restrict__ out)
{
    const int jl = threadIdx.x & 31;
    const int sq = threadIdx.x >> 5;      // 0..3
    const int j  = blockIdx.x * RJ + jl;

    float acc[6] = {0.f, 0.f, 0.f, 0.f, 0.f, 0.f};
#pragma unroll
    for (int k = 0; k < SSLICE; ++k) {
        const int s = sq * SSLICE + k;
        if (s < SPLITS) {
            const float* p = g_part + (size_t)s * 6 * NP + j;
#pragma unroll
            for (int c = 0; c < 6; ++c)
                acc[c] += p[c * NP];
        }
    }

    __shared__ float sh[4][RJ][6];
#pragma unroll
    for (int c = 0; c < 6; ++c) sh[sq][jl][c] = acc[c];
    __syncthreads();

    __shared__ float shpot[TPB2];
    float potj = 0.f;

    if (sq == 0) {
#pragma unroll
        for (int g2 = 1; g2 < 4; ++g2)
#pragma unroll
            for (int c = 0; c < 6; ++c) acc[c] += sh[g2][jl][c];

        const float a1 = acc[0], a2 = acc[1];
        const float fx = acc[2], fy = acc[3], fz = acc[4], dd = acc[5];

        const float ka = kappa[j];
        const float al = alpha[j];
        const float qj = q[j];

        const float ephi = NC * (a1 + a2);
        const float qind = -ka * ephi;
        const float efx = NC * fx, efy = NC * fy, efz = NC * fz;

        out[1 + j] = qind;
        out[1 + NP + 3*j + 0] = al * efx;
        out[1 + NP + 3*j + 1] = al * efy;
        out[1 + NP + 3*j + 2] = al * efz;

        potj = qj * NC * (0.5f * a1 + a2)
             - 0.5f * NC * dd
             - 0.5f * ka * ephi * ephi
             - 0.5f * al * (efx * efx + efy * efy + efz * efz);
    }

    __shared__ bool lastblk;
    shpot[threadIdx.x] = potj;
    __syncthreads();
#pragma unroll
    for (int ofs = TPB2 / 2; ofs > 0; ofs >>= 1) {
        if (threadIdx.x < ofs) shpot[threadIdx.x] += shpot[threadIdx.x + ofs];
        __syncthreads();
    }
    if (threadIdx.x == 0) {
        g_potblk[blockIdx.x] = shpot[0];
        __threadfence();
        const int old = atomicAdd(&g_sem, 1);
        lastblk = (old == RBLK - 1);
    }
    __syncthreads();

    if (lastblk) {
        __threadfence();
        float v = (threadIdx.x < RBLK) ? g_potblk[threadIdx.x] : 0.f;
        shpot[threadIdx.x] = v;
        __syncthreads();
#pragma unroll
        for (int ofs = TPB2 / 2; ofs > 0; ofs >>= 1) {
            if (threadIdx.x < ofs) shpot[threadIdx.x] += shpot[threadIdx.x + ofs];
            __syncthreads();
        }
        if (threadIdx.x == 0) {
            out[0] = shpot[0];
            g_sem = 0;    // reset for next graph replay
        }
    }
}

extern "C" void kernel_launch(void* const* d_in, const int* in_sizes, int n_in,
                              void* d_out, int out_size)
{
    const float* q     = (const float*)d_in[0];
    const float* r     = (const float*)d_in[1];
    const float* u     = (const float*)d_in[4];
    const float* kappa = (const float*)d_in[5];
    const float* alpha = (const float*)d_in[6];
    float* out = (float*)d_out;

    dim3 grid1(JBLK, SPLITS);
    ewald_pair_kernel<<<grid1, TPB>>>(q, r, u);
    ewald_reduce_kernel<<<RBLK, TPB2>>>(q, kappa, alpha, out);
}

// round 7
// speedup vs baseline: 1.7788x; 1.0865x over previous
#include <cuda_runtime.h>

#define NP      3072
#define SPLITS  37
#define CHUNK   84              // 37*84 = 3108 >= 3072 (padded)
#define HC      (CHUNK / 2)     // 42 packed iterations
#define TPB     128
#define JBLK    (NP / TPB)      // 24 -> grid = 24*37 = 888 = 6*148 blocks

#define RJ      32              // j per reduce block
#define RBLK    (NP / RJ)       // 96 reduce blocks
#define TPB2    192             // 6 warps: one component each for 32 j's

// constants (sigma = 1, A = 1/sqrt(2), A^2 = 1/2)
#define A_CONST 0.7071067811865476f
#define C1      0.7978845608028654f     // 2A/sqrt(pi) == 4A^3/sqrt(pi) since A^2=1/2
#define NC      14.399645f              // 90.4756 / (2*pi)
// Abramowitz-Stegun 7.1.26 erfc: erfc(x) = g*t*P(t), t=1/(1+p*x), |err|<=1.5e-7
#define P_AS  0.3275911f
#define PA    (P_AS * A_CONST)
#define AS1   0.254829592f
#define AS2  -0.284496736f
#define AS3   1.421413741f
#define AS4  -1.453152027f
#define AS5   1.061405429f
#define NL2E_HALF (-0.7213475204444817f)  // -0.5*log2(e)
#define RCUT2     20.25f                   // beyond this erf=1,g=0 to ~1e-4 rel
#define RINV_CUT  0.2222f                  // 1/sqrt(RCUT2)

typedef unsigned long long u64;

__device__ float g_part[SPLITS * 6 * NP];
__device__ float g_potblk[RBLK];
__device__ int   g_sem;

__device__ __forceinline__ float rcp_fast(float x) {
    float y; asm("rcp.approx.f32 %0, %1;" : "=f"(y) : "f"(x)); return y;
}
__device__ __forceinline__ float ex2_fast(float x) {
    float y; asm("ex2.approx.f32 %0, %1;" : "=f"(y) : "f"(x)); return y;
}
__device__ __forceinline__ u64 pk(float lo, float hi) {
    u64 r; asm("mov.b64 %0, {%1, %2};" : "=l"(r) : "f"(lo), "f"(hi)); return r;
}
__device__ __forceinline__ void upk(u64 a, float& lo, float& hi) {
    asm("mov.b64 {%0, %1}, %2;" : "=f"(lo), "=f"(hi) : "l"(a));
}
__device__ __forceinline__ u64 fma2(u64 a, u64 b, u64 c) {
    u64 d; asm("fma.rn.f32x2 %0, %1, %2, %3;" : "=l"(d) : "l"(a), "l"(b), "l"(c)); return d;
}
__device__ __forceinline__ u64 mul2(u64 a, u64 b) {
    u64 d; asm("mul.rn.f32x2 %0, %1, %2;" : "=l"(d) : "l"(a), "l"(b)); return d;
}
__device__ __forceinline__ u64 add2(u64 a, u64 b) {
    u64 d; asm("add.rn.f32x2 %0, %1, %2;" : "=l"(d) : "l"(a), "l"(b)); return d;
}

// scalar correction for one near pair: add (true - bare) terms; everything ~ g
__device__ __forceinline__ void corr_half(
    float dx, float dy, float dz, float qi,
    float ux, float uy, float uz, bool act,
    float& A1, float& A2,
    float& Hx, float& Hy, float& Hz,
    float& Wx, float& Wy, float& Wz,
    float& Gx, float& Gy, float& Gz)
{
    float t0 = dx * dx;
    t0 = fmaf(dy, dy, t0);
    const float d2 = fmaf(dz, dz, t0);
    const bool on = act && (d2 != 0.f) && (d2 < RCUT2);
    const float d2s  = fmaxf(d2, 1e-8f);
    const float rinv = rsqrtf(d2s);
    const float m    = on ? 1.f : 0.f;
    const float g    = ex2_fast(NL2E_HALF * d2s) * m;
    const float rn   = d2s * rinv;
    const float tt   = rcp_fast(fmaf(PA, rn, 1.f));
    const float poly = fmaf(fmaf(fmaf(fmaf(AS5, tt, AS4), tt, AS3), tt, AS2), tt, AS1);
    const float erfc = g * tt * poly;
    const float de   = -erfc * rinv;
    const float rr   = rinv * rinv;
    const float c1g  = C1 * g;
    const float ds1  = (de - c1g) * rr;
    const float uri  = fmaf(ux, dx, fmaf(uy, dy, uz * dz));
    const float ds2r = fmaf(3.f, ds1, -c1g) * (uri * rr);
    A1 = fmaf(qi, de, A1);
    A2 = fmaf(ds1, uri, A2);
    Hx = fmaf(ds2r, dx, Hx); Hy = fmaf(ds2r, dy, Hy); Hz = fmaf(ds2r, dz, Hz);
    const float qd = qi * ds1;
    Wx = fmaf(qd, dx, Wx); Wy = fmaf(qd, dy, Wy); Wz = fmaf(qd, dz, Wz);
    Gx = fmaf(ds1, ux, Gx); Gy = fmaf(ds1, uy, Gy); Gz = fmaf(ds1, uz, Gz);
}

__global__ __launch_bounds__(TPB, 6)
void ewald_pair_kernel(const float* __restrict__ q,
                       const float* __restrict__ r,
                       const float* __restrict__ u)
{
    const int j  = blockIdx.x * TPB + threadIdx.x;
    const int s  = blockIdx.y;
    const int i0 = s * CHUNK;

    __shared__ ulonglong2 s_p0[HC];   // {-rx2, -ry2}
    __shared__ ulonglong2 s_p1[HC];   // {-rz2,   q2}
    __shared__ ulonglong2 s_p2[HC];   // { ux2,  uy2}
    __shared__ u64        s_p3[HC];   // { uz2 }

    for (int t = threadIdx.x; t < HC; t += TPB) {
        const int ia = i0 + t;
        const int ib = ia + HC;
        float rxa, rya, rza, qa, uxa, uya, uza;
        float rxb, ryb, rzb, qb, uxb, uyb, uzb;
        if (ia < NP) {
            rxa = r[3*ia+0]; rya = r[3*ia+1]; rza = r[3*ia+2];
            qa = q[ia]; uxa = u[3*ia+0]; uya = u[3*ia+1]; uza = u[3*ia+2];
        } else { rxa=1e4f; rya=1e4f; rza=1e4f; qa=0.f; uxa=0.f; uya=0.f; uza=0.f; }
        if (ib < NP) {
            rxb = r[3*ib+0]; ryb = r[3*ib+1]; rzb = r[3*ib+2];
            qb = q[ib]; uxb = u[3*ib+0]; uyb = u[3*ib+1]; uzb = u[3*ib+2];
        } else { rxb=1e4f; ryb=1e4f; rzb=1e4f; qb=0.f; uxb=0.f; uyb=0.f; uzb=0.f; }
        s_p0[t] = make_ulonglong2(pk(-rxa, -rxb), pk(-rya, -ryb));
        s_p1[t] = make_ulonglong2(pk(-rza, -rzb), pk(qa, qb));
        s_p2[t] = make_ulonglong2(pk(uxa, uxb), pk(uya, uyb));
        s_p3[t] = pk(uza, uzb);
    }
    __syncthreads();

    const float rjx = r[3*j+0], rjy = r[3*j+1], rjz = r[3*j+2];
    const float ujx = u[3*j+0], ujy = u[3*j+1], ujz = u[3*j+2];

    const u64 rjx2 = pk(rjx, rjx), rjy2 = pk(rjy, rjy), rjz2 = pk(rjz, rjz);
    const u64 kThree = 0x4040000040400000ull;

    u64 a1 = 0, a2 = 0;
    u64 hx = 0, hy = 0, hz = 0;
    u64 wx = 0, wy = 0, wz = 0;
    u64 gx = 0, gy = 0, gz = 0;
    u64 mask = 0;

    // ---------------- Pass A: bare Coulomb (erf=1, g=0) for ALL pairs ----------------
#pragma unroll 6
    for (int t = 0; t < HC; ++t) {
        const ulonglong2 p0 = s_p0[t];
        const ulonglong2 p1 = s_p1[t];
        const ulonglong2 p2 = s_p2[t];
        const u64 uz2 = s_p3[t];

        const u64 dx = add2(rjx2, p0.x);
        const u64 dy = add2(rjy2, p0.y);
        const u64 dz = add2(rjz2, p1.x);
        u64 d2 = mul2(dx, dx);
        d2 = fma2(dy, dy, d2);
        d2 = fma2(dz, dz, d2);

        float d2l, d2h; upk(d2, d2l, d2h);
        float rl = rsqrtf(d2l), rh = rsqrtf(d2h);
        rl = (d2l == 0.f) ? 0.f : rl;
        rh = (d2h == 0.f) ? 0.f : rh;
        const bool near = fmaxf(rl, rh) > RINV_CUT;
        mask |= ((u64)near) << t;

        const u64 rinv = pk(rl, rh);
        const u64 rr   = mul2(rinv, rinv);
        const u64 s1   = mul2(rinv, rr);

        a1 = fma2(p1.y, rinv, a1);

        u64 uri = mul2(p2.x, dx);
        uri = fma2(p2.y, dy, uri);
        uri = fma2(uz2, dz, uri);
        a2 = fma2(s1, uri, a2);

        const u64 v   = mul2(uri, rr);
        const u64 v3  = mul2(v, kThree);
        const u64 s2r = mul2(s1, v3);

        hx = fma2(s2r, dx, hx);
        hy = fma2(s2r, dy, hy);
        hz = fma2(s2r, dz, hz);
        const u64 qs1 = mul2(p1.y, s1);
        wx = fma2(qs1, dx, wx);
        wy = fma2(qs1, dy, wy);
        wz = fma2(qs1, dz, wz);
        gx = fma2(s1, p2.x, gx);
        gy = fma2(s1, p2.y, gy);
        gz = fma2(s1, uz2, gz);
    }

    float l, h;
    upk(a1, l, h); float A1 = l + h;
    upk(a2, l, h); float A2 = l + h;
    upk(hx, l, h); float Hx = l + h;
    upk(hy, l, h); float Hy = l + h;
    upk(hz, l, h); float Hz = l + h;
    upk(wx, l, h); float Wx = l + h;
    upk(wy, l, h); float Wy = l + h;
    upk(wz, l, h); float Wz = l + h;
    upk(gx, l, h); float Gx = l + h;
    upk(gy, l, h); float Gy = l + h;
    upk(gz, l, h); float Gz = l + h;

    // ---------------- Pass B: sparse erf/gauss corrections for near pairs ----------------
    unsigned mlo = (unsigned)mask;
    unsigned mhi = (unsigned)(mask >> 32);
    while (__any_sync(0xFFFFFFFFu, mlo | mhi)) {
        const bool act = (mlo | mhi) != 0u;
        int t = 0;
        if (mlo) { t = __ffs(mlo) - 1;  mlo &= mlo - 1u; }
        else if (mhi) { t = __ffs(mhi) + 31; mhi &= mhi - 1u; }

        const ulonglong2 p0 = s_p0[t];
        const ulonglong2 p1 = s_p1[t];
        const ulonglong2 p2 = s_p2[t];
        const u64 uz2 = s_p3[t];
        float nrxl, nrxh, nryl, nryh, nrzl, nrzh, ql, qh;
        float uxl, uxh, uyl, uyh, uzl, uzh;
        upk(p0.x, nrxl, nrxh); upk(p0.y, nryl, nryh);
        upk(p1.x, nrzl, nrzh); upk(p1.y, ql, qh);
        upk(p2.x, uxl, uxh);   upk(p2.y, uyl, uyh);
        upk(uz2, uzl, uzh);

        corr_half(rjx + nrxl, rjy + nryl, rjz + nrzl, ql, uxl, uyl, uzl, act,
                  A1, A2, Hx, Hy, Hz, Wx, Wy, Wz, Gx, Gy, Gz);
        corr_half(rjx + nrxh, rjy + nryh, rjz + nrzh, qh, uxh, uyh, uzh, act,
                  A1, A2, Hx, Hy, Hz, Wx, Wy, Wz, Gx, Gy, Gz);
    }

    const float Mx = Hx - Gx, My = Hy - Gy, Mz = Hz - Gz;
    const float fx = Wx + Mx, fy = Wy + My, fz = Wz + Mz;
    const float dd = ujx * Mx + ujy * My + ujz * Mz;

    float* p = g_part + (size_t)s * 6 * NP;
    p[0*NP + j] = A1;
    p[1*NP + j] = A2;
    p[2*NP + j] = fx;
    p[3*NP + j] = fy;
    p[4*NP + j] = fz;
    p[5*NP + j] = dd;
}

// 96 blocks x 192 threads: warp c (0..5) sums component c for 32 j's.
// Each thread: 37 fully-independent unpredicated loads -> max MLP.
__global__ __launch_bounds__(TPB2)
void ewald_reduce_kernel(const float* __restrict__ q,
                         const float* __restrict__ kappa,
                         const float* __restrict__ alpha,
                         float* __restrict__ out)
{
    const int jl = threadIdx.x & 31;
    const int c  = threadIdx.x >> 5;      // 0..5 component
    const int j  = blockIdx.x * RJ + jl;

    const float* base = g_part + (size_t)c * NP + j;
    float acc = 0.f;
#pragma unroll
    for (int s = 0; s < SPLITS; ++s)
        acc += base[(size_t)s * 6 * NP];

    __shared__ float sh[6][RJ];
    sh[c][jl] = acc;
    __syncthreads();

    float potj = 0.f;
    if (c == 0) {
        const float a1 = sh[0][jl], a2 = sh[1][jl];
        const float fx = sh[2][jl], fy = sh[3][jl], fz = sh[4][jl], dd = sh[5][jl];

        const float ka = kappa[j];
        const float al = alpha[j];
        const float qj = q[j];

        const float ephi = NC * (a1 + a2);
        const float qind = -ka * ephi;
        const float efx = NC * fx, efy = NC * fy, efz = NC * fz;

        out[1 + j] = qind;
        out[1 + NP + 3*j + 0] = al * efx;
        out[1 + NP + 3*j + 1] = al * efy;
        out[1 + NP + 3*j + 2] = al * efz;

        potj = qj * NC * (0.5f * a1 + a2)
             - 0.5f * NC * dd
             - 0.5f * ka * ephi * ephi
             - 0.5f * al * (efx * efx + efy * efy + efz * efz);

        // warp-local reduction of potj (warp 0 only)
#pragma unroll
        for (int ofs = 16; ofs > 0; ofs >>= 1)
            potj += __shfl_down_sync(0xFFFFFFFFu, potj, ofs);
    }

    __shared__ bool lastblk;
    if (threadIdx.x == 0) {
        g_potblk[blockIdx.x] = potj;
        __threadfence();
        const int old = atomicAdd(&g_sem, 1);
        lastblk = (old == RBLK - 1);
    }
    __syncthreads();

    if (lastblk && threadIdx.x < 32) {
        __threadfence();
        const int t = threadIdx.x;
        // 96 = 3*32: each lane sums exactly 3 entries, then shuffle-reduce
        float v = g_potblk[t] + g_potblk[t + 32] + g_potblk[t + 64];
#pragma unroll
        for (int ofs = 16; ofs > 0; ofs >>= 1)
            v += __shfl_down_sync(0xFFFFFFFFu, v, ofs);
        if (t == 0) {
            out[0] = v;
            g_sem = 0;    // reset for next graph replay
        }
    }
}

extern "C" void kernel_launch(void* const* d_in, const int* in_sizes, int n_in,
                              void* d_out, int out_size)
{
    const float* q     = (const float*)d_in[0];
    const float* r     = (const float*)d_in[1];
    const float* u     = (const float*)d_in[4];
    const float* kappa = (const float*)d_in[5];
    const float* alpha = (const float*)d_in[6];
    float* out = (float*)d_out;

    dim3 grid1(JBLK, SPLITS);
    ewald_pair_kernel<<<grid1, TPB>>>(q, r, u);
    ewald_reduce_kernel<<<RBLK, TPB2>>>(q, kappa, alpha, out);
}